// round 4
// baseline (speedup 1.0000x reference)
#include <cuda_runtime.h>
#include <math.h>

// Problem shape (fixed by setup_inputs): pred/target (32,1,1024,1024) f32.
#define Wd   1024
#define Hd   1024
#define Bd   32
#define RPB  32                       // rows per block
#define GRPS (Hd / RPB)               // 32 row-groups per image
#define NBLK (Bd * GRPS)              // 1024 blocks
#define NTHR 256                      // 8 warps * 128 cols = 1024 cols

#define BW 3.0f                       // boundary weight
#define NEG_BIG (-1.0e30f)
#define POS_BIG ( 1.0e30f)
#define FULLM 0xFFFFFFFFu

__device__ float        g_partials[NBLK];
__device__ unsigned int g_ticket;     // zero-initialized; reset by last block

__device__ __forceinline__ float max3(float a, float b, float c) {
    return fmaxf(fmaxf(a, b), c);
}
__device__ __forceinline__ float min3(float a, float b, float c) {
    return fminf(fminf(a, b), c);
}

__global__ __launch_bounds__(NTHR)
void bab_fused(const float* __restrict__ pred, const float* __restrict__ target,
               float* __restrict__ out)
{
    const int tid  = threadIdx.x;
    const int lane = tid & 31;
    const int warp = tid >> 5;

    const int grp = blockIdx.x;
    const int img = grp / GRPS;
    const int y0  = (grp % GRPS) * RPB;

    const int x0 = warp * 128 + lane * 4;     // this thread's 4 columns
    const int xL = warp * 128 - 1;            // halo col (lane 0 only)
    const int xR = warp * 128 + 128;          // halo col (lane 31 only)
    const bool doL = (lane == 0)  && (xL >= 0);
    const bool doR = (lane == 31) && (xR < Wd);

    const float* __restrict__ tb = target + (size_t)img * Hd * Wd;
    const float* __restrict__ pb = pred   + (size_t)img * Hd * Wd;

    // Rolling 3-row register window of target (float4 per thread) +
    // rolling scalar halo windows on the edge lanes.
    // Border rows via index CLAMP (not predication): clamped row == cur row,
    // which is exactly the pooling identity we need -> unconditional loads.
    const int ypInit = (y0 > 0) ? (y0 - 1) : 0;
    float4 cur  = *(const float4*)(tb + (size_t)y0 * Wd + x0);
    float4 prev = *(const float4*)(tb + (size_t)ypInit * Wd + x0);

    float curL = 0.f, prevL = 0.f, curR = 0.f, prevR = 0.f;
    if (doL) { curL  = tb[(size_t)y0 * Wd + xL];
               prevL = tb[(size_t)ypInit * Wd + xL]; }
    if (doR) { curR  = tb[(size_t)y0 * Wd + xR];
               prevR = tb[(size_t)ypInit * Wd + xR]; }

    float acc = 0.0f;

    #pragma unroll 4
    for (int r = 0; r < RPB; ++r) {
        const int y  = y0 + r;
        const int yn = (y + 1 < Hd) ? (y + 1) : y;   // clamp: border -> next==cur

        // Issue all memory up front (unconditional, affine -> batched by ptxas).
        const float4 next = *(const float4*)(tb + (size_t)yn * Wd + x0);
        const float4 p    = __ldcs((const float4*)(pb + (size_t)y * Wd + x0));
        const float nextL = doL ? tb[(size_t)yn * Wd + xL] : 0.f;
        const float nextR = doR ? tb[(size_t)yn * Wd + xR] : 0.f;

        // Vertical 3-tap extremes.
        float4 vmax, vmin;
        vmax.x = max3(prev.x, cur.x, next.x);
        vmax.y = max3(prev.y, cur.y, next.y);
        vmax.z = max3(prev.z, cur.z, next.z);
        vmax.w = max3(prev.w, cur.w, next.w);
        vmin.x = min3(prev.x, cur.x, next.x);
        vmin.y = min3(prev.y, cur.y, next.y);
        vmin.z = min3(prev.z, cur.z, next.z);
        vmin.w = min3(prev.w, cur.w, next.w);

        // Neighbor-column extremes via warp shuffle (lane +/- 1).
        float lMax = __shfl_up_sync(FULLM, vmax.w, 1);
        float lMin = __shfl_up_sync(FULLM, vmin.w, 1);
        float rMax = __shfl_down_sync(FULLM, vmax.x, 1);
        float rMin = __shfl_down_sync(FULLM, vmin.x, 1);

        if (lane == 0) {
            if (doL) { lMax = max3(prevL, curL, nextL);
                       lMin = min3(prevL, curL, nextL); }
            else     { lMax = NEG_BIG; lMin = POS_BIG; }   // image left border
        }
        if (lane == 31) {
            if (doR) { rMax = max3(prevR, curR, nextR);
                       rMin = min3(prevR, curR, nextR); }
            else     { rMax = NEG_BIG; rMin = POS_BIG; }   // image right border
        }

        // Horizontal 3-tap: dilated/eroded per column, then weight + BCE.
        float d0 = max3(lMax,   vmax.x, vmax.y), e0 = min3(lMin,   vmin.x, vmin.y);
        float d1 = max3(vmax.x, vmax.y, vmax.z), e1 = min3(vmin.x, vmin.y, vmin.z);
        float d2 = max3(vmax.y, vmax.z, vmax.w), e2 = min3(vmin.y, vmin.z, vmin.w);
        float d3 = max3(vmax.z, vmax.w, rMax),   e3 = min3(vmin.z, vmin.w, rMin);

        float w0 = (d0 - e0 > 0.5f) ? BW : 1.0f;
        float w1 = (d1 - e1 > 0.5f) ? BW : 1.0f;
        float w2 = (d2 - e2 > 0.5f) ? BW : 1.0f;
        float w3 = (d3 - e3 > 0.5f) ? BW : 1.0f;

        // target is exactly 0 or 1 -> BCE collapses to a select of one log.
        float l0 = (cur.x > 0.5f) ? (-__logf(p.x)) : (-__logf(fmaxf(1.0f - p.x, 1e-30f)));
        float l1 = (cur.y > 0.5f) ? (-__logf(p.y)) : (-__logf(fmaxf(1.0f - p.y, 1e-30f)));
        float l2 = (cur.z > 0.5f) ? (-__logf(p.z)) : (-__logf(fmaxf(1.0f - p.z, 1e-30f)));
        float l3 = (cur.w > 0.5f) ? (-__logf(p.w)) : (-__logf(fmaxf(1.0f - p.w, 1e-30f)));

        acc = fmaf(w0, l0, acc);
        acc = fmaf(w1, l1, acc);
        acc = fmaf(w2, l2, acc);
        acc = fmaf(w3, l3, acc);

        prev = cur;  cur  = next;
        prevL = curL; curL = nextL;
        prevR = curR; curR = nextR;
    }

    // ---- Block reduction: warp shuffle, then cross-warp via shared. ----
    #pragma unroll
    for (int off = 16; off > 0; off >>= 1)
        acc += __shfl_down_sync(FULLM, acc, off);

    __shared__ float swarp[NTHR / 32];
    if (lane == 0) swarp[warp] = acc;
    __syncthreads();
    if (tid == 0) {
        float v = 0.0f;
        #pragma unroll
        for (int i = 0; i < NTHR / 32; ++i) v += swarp[i];
        g_partials[blockIdx.x] = v;
    }

    // ---- Last-block fused finalize (deterministic order). ----
    __shared__ bool s_last;
    __threadfence();
    if (tid == 0) {
        unsigned int old = atomicAdd(&g_ticket, 1u);
        s_last = (old == NBLK - 1);
    }
    __syncthreads();

    if (s_last) {
        __shared__ double sd[NTHR];
        double s = 0.0;
        for (int i = tid; i < NBLK; i += NTHR)   // fixed order per thread
            s += (double)g_partials[i];
        sd[tid] = s;
        __syncthreads();
        #pragma unroll
        for (int stride = NTHR / 2; stride > 0; stride >>= 1) {
            if (tid < stride) sd[tid] += sd[tid + stride];
            __syncthreads();
        }
        if (tid == 0) {
            out[0] = (float)(sd[0] / (double)((size_t)Bd * Hd * Wd));
            g_ticket = 0;                        // reset for next launch/replay
        }
    }
}

extern "C" void kernel_launch(void* const* d_in, const int* in_sizes, int n_in,
                              void* d_out, int out_size)
{
    (void)in_sizes; (void)n_in; (void)out_size;
    const float* pred   = (const float*)d_in[0];
    const float* target = (const float*)d_in[1];
    float* out = (float*)d_out;

    bab_fused<<<NBLK, NTHR>>>(pred, target, out);
}

// round 5
// speedup vs baseline: 1.0237x; 1.0237x over previous
#include <cuda_runtime.h>
#include <math.h>

// Problem shape (fixed by setup_inputs): pred/target (32,1,1024,1024) f32.
#define Wd   1024
#define Hd   1024
#define Bd   32
#define RPB  32                       // rows per block
#define GRPS (Hd / RPB)               // 32 row-groups per image
#define NBLK (Bd * GRPS)              // 1024 blocks
#define NTHR 256                      // 8 warps * 128 cols = 1024 cols

#define NEG_BIG (-1.0e30f)
#define POS_BIG ( 1.0e30f)
#define FULLM 0xFFFFFFFFu
#define NLN2  (-0.69314718055994530942f)

__device__ float        g_partials[NBLK];
__device__ unsigned int g_ticket;     // zero-init; reset by last block

__device__ __forceinline__ float max3(float a, float b, float c) {
    return fmaxf(fmaxf(a, b), c);
}
__device__ __forceinline__ float min3(float a, float b, float c) {
    return fminf(fminf(a, b), c);
}

// Per-row contribution: Sum_i w_i * log2(1-|t_i-p_i|), w_i = 1+2*boundary_i.
// eL*/eR* are the halo-column vertical extremes (valid on lane 0 / lane 31;
// NEG_BIG/POS_BIG identities at the image border).
__device__ __forceinline__ float row_loss(
    const float4 vmax, const float4 vmin, const float4 t, const float4 p,
    float eLMax, float eLMin, float eRMax, float eRMin, int lane)
{
    float lMax = __shfl_up_sync(FULLM, vmax.w, 1);
    float lMin = __shfl_up_sync(FULLM, vmin.w, 1);
    float rMax = __shfl_down_sync(FULLM, vmax.x, 1);
    float rMin = __shfl_down_sync(FULLM, vmin.x, 1);
    if (lane == 0)  { lMax = eLMax; lMin = eLMin; }
    if (lane == 31) { rMax = eRMax; rMin = eRMin; }

    // boundary indicator: dilated - eroded, exactly 0.0 or 1.0 (binary mask)
    float b0 = max3(lMax,   vmax.x, vmax.y) - min3(lMin,   vmin.x, vmin.y);
    float b1 = max3(vmax.x, vmax.y, vmax.z) - min3(vmin.x, vmin.y, vmin.z);
    float b2 = max3(vmax.y, vmax.z, vmax.w) - min3(vmin.y, vmin.z, vmin.w);
    float b3 = max3(vmax.z, vmax.w, rMax)   - min3(vmin.z, vmin.w, rMin);

    // arg = 1-|t-p| == (t ? p : 1-p) exactly; pred in (1e-6, 1-1e-6) => arg>0.
    float s;
    s  = fmaf(2.0f, b0, 1.0f) * __log2f(1.0f - fabsf(t.x - p.x));
    s += fmaf(2.0f, b1, 1.0f) * __log2f(1.0f - fabsf(t.y - p.y));
    s += fmaf(2.0f, b2, 1.0f) * __log2f(1.0f - fabsf(t.z - p.z));
    s += fmaf(2.0f, b3, 1.0f) * __log2f(1.0f - fabsf(t.w - p.w));
    return s;
}

__global__ __launch_bounds__(NTHR)
void bab_fused(const float* __restrict__ pred, const float* __restrict__ target,
               float* __restrict__ out)
{
    const int tid  = threadIdx.x;
    const int lane = tid & 31;
    const int warp = tid >> 5;

    const int grp = blockIdx.x;
    const int img = grp / GRPS;
    const int y0  = (grp % GRPS) * RPB;

    const int x0 = warp * 128 + lane * 4;     // this thread's 4 columns
    const int xL = warp * 128 - 1;            // halo col (lane 0 only)
    const int xR = warp * 128 + 128;          // halo col (lane 31 only)
    const bool doL = (lane == 0)  && (xL >= 0);
    const bool doR = (lane == 31) && (xR < Wd);

    const float* __restrict__ tb = target + (size_t)img * Hd * Wd;
    const float* __restrict__ pb = pred   + (size_t)img * Hd * Wd;

    // Rolling register window of target rows: prev (y-1), cur (y).
    // Border rows via index clamp (clamped row == pooling identity).
    const int ypInit = (y0 > 0) ? (y0 - 1) : 0;
    float4 cur  = *(const float4*)(tb + (size_t)y0 * Wd + x0);
    float4 prev = *(const float4*)(tb + (size_t)ypInit * Wd + x0);

    float curL = 0.f, prevL = 0.f, curR = 0.f, prevR = 0.f;
    if (doL) { curL  = tb[(size_t)y0 * Wd + xL];
               prevL = tb[(size_t)ypInit * Wd + xL]; }
    if (doR) { curR  = tb[(size_t)y0 * Wd + xR];
               prevR = tb[(size_t)ypInit * Wd + xR]; }

    float acc = 0.0f;

    // Two rows per iteration; pairwise-shared vertical extremes.
    #pragma unroll 2
    for (int r = 0; r < RPB; r += 2) {
        const int y   = y0 + r;
        const int yn1 = y + 1;                            // always < Hd in-block
        const int yn2 = (y + 2 < Hd) ? (y + 2) : (Hd - 1); // clamp -> == yn1 row

        // All loads up front (affine, unconditional for the float4s).
        const float4 nextA = *(const float4*)(tb + (size_t)yn1 * Wd + x0);
        const float4 nextB = *(const float4*)(tb + (size_t)yn2 * Wd + x0);
        const float4 pA    = *(const float4*)(pb + (size_t)y   * Wd + x0);
        const float4 pB    = *(const float4*)(pb + (size_t)yn1 * Wd + x0);
        const float nextAL = doL ? tb[(size_t)yn1 * Wd + xL] : 0.f;
        const float nextBL = doL ? tb[(size_t)yn2 * Wd + xL] : 0.f;
        const float nextAR = doR ? tb[(size_t)yn1 * Wd + xR] : 0.f;
        const float nextBR = doR ? tb[(size_t)yn2 * Wd + xR] : 0.f;

        // Shared pair extremes of (cur, nextA).
        float4 pmx, pmn;
        pmx.x = fmaxf(cur.x, nextA.x); pmn.x = fminf(cur.x, nextA.x);
        pmx.y = fmaxf(cur.y, nextA.y); pmn.y = fminf(cur.y, nextA.y);
        pmx.z = fmaxf(cur.z, nextA.z); pmn.z = fminf(cur.z, nextA.z);
        pmx.w = fmaxf(cur.w, nextA.w); pmn.w = fminf(cur.w, nextA.w);

        // Row A vertical extremes: (prev, cur, nextA) = op(prev, pair).
        float4 vmaxA, vminA, vmaxB, vminB;
        vmaxA.x = fmaxf(prev.x, pmx.x); vminA.x = fminf(prev.x, pmn.x);
        vmaxA.y = fmaxf(prev.y, pmx.y); vminA.y = fminf(prev.y, pmn.y);
        vmaxA.z = fmaxf(prev.z, pmx.z); vminA.z = fminf(prev.z, pmn.z);
        vmaxA.w = fmaxf(prev.w, pmx.w); vminA.w = fminf(prev.w, pmn.w);
        // Row B vertical extremes: (cur, nextA, nextB) = op(pair, nextB).
        vmaxB.x = fmaxf(nextB.x, pmx.x); vminB.x = fminf(nextB.x, pmn.x);
        vmaxB.y = fmaxf(nextB.y, pmx.y); vminB.y = fminf(nextB.y, pmn.y);
        vmaxB.z = fmaxf(nextB.z, pmx.z); vminB.z = fminf(nextB.z, pmn.z);
        vmaxB.w = fmaxf(nextB.w, pmx.w); vminB.w = fminf(nextB.w, pmn.w);

        // Halo-column vertical extremes (meaningful on edge lanes only).
        const float eLMaxA = doL ? max3(prevL, curL, nextAL) : NEG_BIG;
        const float eLMinA = doL ? min3(prevL, curL, nextAL) : POS_BIG;
        const float eRMaxA = doR ? max3(prevR, curR, nextAR) : NEG_BIG;
        const float eRMinA = doR ? min3(prevR, curR, nextAR) : POS_BIG;
        const float eLMaxB = doL ? max3(curL, nextAL, nextBL) : NEG_BIG;
        const float eLMinB = doL ? min3(curL, nextAL, nextBL) : POS_BIG;
        const float eRMaxB = doR ? max3(curR, nextAR, nextBR) : NEG_BIG;
        const float eRMinB = doR ? min3(curR, nextAR, nextBR) : POS_BIG;

        acc += row_loss(vmaxA, vminA, cur,   pA, eLMaxA, eLMinA, eRMaxA, eRMinA, lane);
        acc += row_loss(vmaxB, vminB, nextA, pB, eLMaxB, eLMinB, eRMaxB, eRMinB, lane);

        prev = nextA;  cur = nextB;
        prevL = nextAL; curL = nextBL;
        prevR = nextAR; curR = nextBR;
    }

    acc *= NLN2;   // one scale: sum of w*log2(arg) -> sum of w*(-ln(arg))

    // ---- Block reduction: warp shuffle, then cross-warp via shared. ----
    #pragma unroll
    for (int off = 16; off > 0; off >>= 1)
        acc += __shfl_down_sync(FULLM, acc, off);

    __shared__ float swarp[NTHR / 32];
    if (lane == 0) swarp[warp] = acc;
    __syncthreads();
    if (tid == 0) {
        float v = 0.0f;
        #pragma unroll
        for (int i = 0; i < NTHR / 32; ++i) v += swarp[i];
        g_partials[blockIdx.x] = v;
    }

    // ---- Last-block fused finalize (deterministic order). ----
    __shared__ bool s_last;
    __threadfence();
    if (tid == 0) {
        unsigned int old = atomicAdd(&g_ticket, 1u);
        s_last = (old == NBLK - 1);
    }
    __syncthreads();

    if (s_last) {
        __shared__ double sd[NTHR];
        double s = 0.0;
        for (int i = tid; i < NBLK; i += NTHR)   // fixed order per thread
            s += (double)g_partials[i];
        sd[tid] = s;
        __syncthreads();
        #pragma unroll
        for (int stride = NTHR / 2; stride > 0; stride >>= 1) {
            if (tid < stride) sd[tid] += sd[tid + stride];
            __syncthreads();
        }
        if (tid == 0) {
            out[0] = (float)(sd[0] / (double)((size_t)Bd * Hd * Wd));
            g_ticket = 0;                        // reset for next launch/replay
        }
    }
}

extern "C" void kernel_launch(void* const* d_in, const int* in_sizes, int n_in,
                              void* d_out, int out_size)
{
    (void)in_sizes; (void)n_in; (void)out_size;
    const float* pred   = (const float*)d_in[0];
    const float* target = (const float*)d_in[1];
    float* out = (float*)d_out;

    bab_fused<<<NBLK, NTHR>>>(pred, target, out);
}

// round 6
// speedup vs baseline: 1.0508x; 1.0265x over previous
#include <cuda_runtime.h>
#include <math.h>

// Problem shape (fixed by setup_inputs): pred/target (32,1,1024,1024) f32.
#define Wd   1024
#define Hd   1024
#define Bd   32
#define RPB  32                       // rows per block
#define GRPS (Hd / RPB)               // 32 row-groups per image
#define NBLK (Bd * GRPS)              // 1024 blocks
#define NTHR 256                      // 8 warps * 128 cols = 1024 cols

#define NEG_BIG (-1.0e30f)
#define POS_BIG ( 1.0e30f)
#define FULLM 0xFFFFFFFFu
#define NLN2  (-0.69314718055994530942f)

__device__ float        g_partials[NBLK];
__device__ unsigned int g_ticket;     // zero-init; reset by last block

__device__ __forceinline__ float max3(float a, float b, float c) {
    return fmaxf(fmaxf(a, b), c);
}
__device__ __forceinline__ float min3(float a, float b, float c) {
    return fminf(fminf(a, b), c);
}

// Per-row contribution: Sum_i w_i * log2(1-|t_i-p_i|), w_i = 1+2*boundary_i.
// eMax/eMin: this lane's halo-column vertical extremes — on lane 0 that is
// the LEFT halo column, on lane 31 the RIGHT halo column (identities at the
// image border). Other lanes' values are ignored.
__device__ __forceinline__ float row_loss(
    const float4 vmax, const float4 vmin, const float4 t, const float4 p,
    float eMax, float eMin, int lane)
{
    float lMax = __shfl_up_sync(FULLM, vmax.w, 1);
    float lMin = __shfl_up_sync(FULLM, vmin.w, 1);
    float rMax = __shfl_down_sync(FULLM, vmax.x, 1);
    float rMin = __shfl_down_sync(FULLM, vmin.x, 1);
    if (lane == 0)  { lMax = eMax; lMin = eMin; }
    if (lane == 31) { rMax = eMax; rMin = eMin; }

    // boundary indicator: dilated - eroded, exactly 0.0 or 1.0 (binary mask)
    float b0 = max3(lMax,   vmax.x, vmax.y) - min3(lMin,   vmin.x, vmin.y);
    float b1 = max3(vmax.x, vmax.y, vmax.z) - min3(vmin.x, vmin.y, vmin.z);
    float b2 = max3(vmax.y, vmax.z, vmax.w) - min3(vmin.y, vmin.z, vmin.w);
    float b3 = max3(vmax.z, vmax.w, rMax)   - min3(vmin.z, vmin.w, rMin);

    // arg = 1-|t-p| == (t ? p : 1-p) exactly; pred in (1e-6, 1-1e-6) => arg>0.
    float s;
    s  = fmaf(2.0f, b0, 1.0f) * __log2f(1.0f - fabsf(t.x - p.x));
    s += fmaf(2.0f, b1, 1.0f) * __log2f(1.0f - fabsf(t.y - p.y));
    s += fmaf(2.0f, b2, 1.0f) * __log2f(1.0f - fabsf(t.z - p.z));
    s += fmaf(2.0f, b3, 1.0f) * __log2f(1.0f - fabsf(t.w - p.w));
    return s;
}

__global__ __launch_bounds__(NTHR, 5)
void bab_fused(const float* __restrict__ pred, const float* __restrict__ target,
               float* __restrict__ out)
{
    const int tid  = threadIdx.x;
    const int lane = tid & 31;
    const int warp = tid >> 5;

    const int grp = blockIdx.x;
    const int img = grp / GRPS;
    const int y0  = (grp % GRPS) * RPB;

    const int x0 = warp * 128 + lane * 4;     // this thread's 4 columns

    // Merged halo: lane 0 tracks the LEFT halo column, lane 31 the RIGHT one.
    // Same registers, different value per lane (register alloc is uniform).
    const int xH  = (lane == 0) ? (warp * 128 - 1) : (warp * 128 + 128);
    const bool doH = ((lane == 0) && (xH >= 0)) || ((lane == 31) && (xH < Wd));
    const float eMaxId = NEG_BIG, eMinId = POS_BIG;   // border identities

    const float* __restrict__ tb = target + (size_t)img * Hd * Wd;
    const float* __restrict__ pb = pred   + (size_t)img * Hd * Wd;

    // Rolling register window of target rows: prev (y-1), cur (y).
    // Border rows via index clamp (clamped row == pooling identity).
    const int ypInit = (y0 > 0) ? (y0 - 1) : 0;
    float4 cur  = *(const float4*)(tb + (size_t)y0 * Wd + x0);
    float4 prev = *(const float4*)(tb + (size_t)ypInit * Wd + x0);

    float curH = 0.f, prevH = 0.f;
    if (doH) { curH  = tb[(size_t)y0 * Wd + xH];
               prevH = tb[(size_t)ypInit * Wd + xH]; }

    float acc = 0.0f;

    // Two rows per iteration; pairwise-shared vertical extremes.
    #pragma unroll 2
    for (int r = 0; r < RPB; r += 2) {
        const int y   = y0 + r;
        const int yn1 = y + 1;                             // always < Hd in-block
        const int yn2 = (y + 2 < Hd) ? (y + 2) : (Hd - 1); // clamp -> identity

        // All loads up front (affine, unconditional for the float4s).
        const float4 nextA = *(const float4*)(tb + (size_t)yn1 * Wd + x0);
        const float4 nextB = *(const float4*)(tb + (size_t)yn2 * Wd + x0);
        const float4 pA    = *(const float4*)(pb + (size_t)y   * Wd + x0);
        const float4 pB    = *(const float4*)(pb + (size_t)yn1 * Wd + x0);
        const float nextAH = doH ? tb[(size_t)yn1 * Wd + xH] : 0.f;
        const float nextBH = doH ? tb[(size_t)yn2 * Wd + xH] : 0.f;

        // Shared pair extremes of (cur, nextA).
        float4 pmx, pmn;
        pmx.x = fmaxf(cur.x, nextA.x); pmn.x = fminf(cur.x, nextA.x);
        pmx.y = fmaxf(cur.y, nextA.y); pmn.y = fminf(cur.y, nextA.y);
        pmx.z = fmaxf(cur.z, nextA.z); pmn.z = fminf(cur.z, nextA.z);
        pmx.w = fmaxf(cur.w, nextA.w); pmn.w = fminf(cur.w, nextA.w);

        // Row A vertical extremes: (prev, cur, nextA) = op(prev, pair).
        float4 vmaxA, vminA, vmaxB, vminB;
        vmaxA.x = fmaxf(prev.x, pmx.x); vminA.x = fminf(prev.x, pmn.x);
        vmaxA.y = fmaxf(prev.y, pmx.y); vminA.y = fminf(prev.y, pmn.y);
        vmaxA.z = fmaxf(prev.z, pmx.z); vminA.z = fminf(prev.z, pmn.z);
        vmaxA.w = fmaxf(prev.w, pmx.w); vminA.w = fminf(prev.w, pmn.w);
        // Row B vertical extremes: (cur, nextA, nextB) = op(pair, nextB).
        vmaxB.x = fmaxf(nextB.x, pmx.x); vminB.x = fminf(nextB.x, pmn.x);
        vmaxB.y = fmaxf(nextB.y, pmx.y); vminB.y = fminf(nextB.y, pmn.y);
        vmaxB.z = fmaxf(nextB.z, pmx.z); vminB.z = fminf(nextB.z, pmn.z);
        vmaxB.w = fmaxf(nextB.w, pmx.w); vminB.w = fminf(nextB.w, pmn.w);

        // Halo-column vertical extremes for this lane's halo column.
        const float eMaxA = doH ? max3(prevH, curH, nextAH) : eMaxId;
        const float eMinA = doH ? min3(prevH, curH, nextAH) : eMinId;
        const float eMaxB = doH ? max3(curH, nextAH, nextBH) : eMaxId;
        const float eMinB = doH ? min3(curH, nextAH, nextBH) : eMinId;

        acc += row_loss(vmaxA, vminA, cur,   pA, eMaxA, eMinA, lane);
        acc += row_loss(vmaxB, vminB, nextA, pB, eMaxB, eMinB, lane);

        prev  = nextA;  cur  = nextB;
        prevH = nextAH; curH = nextBH;
    }

    acc *= NLN2;   // one scale: sum of w*log2(arg) -> sum of w*(-ln(arg))

    // ---- Block reduction: warp shuffle, then cross-warp via shared. ----
    #pragma unroll
    for (int off = 16; off > 0; off >>= 1)
        acc += __shfl_down_sync(FULLM, acc, off);

    __shared__ float swarp[NTHR / 32];
    if (lane == 0) swarp[warp] = acc;
    __syncthreads();
    if (tid == 0) {
        float v = 0.0f;
        #pragma unroll
        for (int i = 0; i < NTHR / 32; ++i) v += swarp[i];
        g_partials[blockIdx.x] = v;
    }

    // ---- Last-block fused finalize (deterministic order). ----
    __shared__ bool s_last;
    __threadfence();
    if (tid == 0) {
        unsigned int old = atomicAdd(&g_ticket, 1u);
        s_last = (old == NBLK - 1);
    }
    __syncthreads();

    if (s_last) {
        __shared__ double sd[NTHR];
        double s = 0.0;
        for (int i = tid; i < NBLK; i += NTHR)   // fixed order per thread
            s += (double)g_partials[i];
        sd[tid] = s;
        __syncthreads();
        #pragma unroll
        for (int stride = NTHR / 2; stride > 0; stride >>= 1) {
            if (tid < stride) sd[tid] += sd[tid + stride];
            __syncthreads();
        }
        if (tid == 0) {
            out[0] = (float)(sd[0] / (double)((size_t)Bd * Hd * Wd));
            g_ticket = 0;                        // reset for next launch/replay
        }
    }
}

extern "C" void kernel_launch(void* const* d_in, const int* in_sizes, int n_in,
                              void* d_out, int out_size)
{
    (void)in_sizes; (void)n_in; (void)out_size;
    const float* pred   = (const float*)d_in[0];
    const float* target = (const float*)d_in[1];
    float* out = (float*)d_out;

    bab_fused<<<NBLK, NTHR>>>(pred, target, out);
}

// round 8
// speedup vs baseline: 1.1076x; 1.0541x over previous
#include <cuda_runtime.h>
#include <math.h>

// Problem shape (fixed by setup_inputs): pred/target (32,1,1024,1024) f32.
#define Wd   1024
#define Hd   1024
#define Bd   32
#define RPB  16                       // rows per block (fine granularity -> small tail)
#define GRPS (Hd / RPB)               // 64 row-groups per image
#define NBLK (Bd * GRPS)              // 2048 blocks
#define NTHR 256                      // 8 warps * 128 cols = 1024 cols

#define NEG_BIG (-1.0e30f)
#define POS_BIG ( 1.0e30f)
#define FULLM 0xFFFFFFFFu
#define NLN2  (-0.69314718055994530942f)

__device__ float        g_partials[NBLK];
__device__ unsigned int g_ticket;     // zero-init; reset by last block

__device__ __forceinline__ float max3(float a, float b, float c) {
    return fmaxf(fmaxf(a, b), c);
}
__device__ __forceinline__ float min3(float a, float b, float c) {
    return fminf(fminf(a, b), c);
}

// Per-row contribution: Sum_i w_i * log2(1-|t_i-p_i|), w_i = 1+2*boundary_i.
// eMax/eMin: this lane's halo-column vertical extremes — on lane 0 the LEFT
// halo column, on lane 31 the RIGHT one (identities at the image border).
__device__ __forceinline__ float row_loss(
    const float4 vmax, const float4 vmin, const float4 t, const float4 p,
    float eMax, float eMin, int lane)
{
    float lMax = __shfl_up_sync(FULLM, vmax.w, 1);
    float lMin = __shfl_up_sync(FULLM, vmin.w, 1);
    float rMax = __shfl_down_sync(FULLM, vmax.x, 1);
    float rMin = __shfl_down_sync(FULLM, vmin.x, 1);
    if (lane == 0)  { lMax = eMax; lMin = eMin; }
    if (lane == 31) { rMax = eMax; rMin = eMin; }

    // boundary indicator: dilated - eroded, exactly 0.0 or 1.0 (binary mask)
    float b0 = max3(lMax,   vmax.x, vmax.y) - min3(lMin,   vmin.x, vmin.y);
    float b1 = max3(vmax.x, vmax.y, vmax.z) - min3(vmin.x, vmin.y, vmin.z);
    float b2 = max3(vmax.y, vmax.z, vmax.w) - min3(vmin.y, vmin.z, vmin.w);
    float b3 = max3(vmax.z, vmax.w, rMax)   - min3(vmin.z, vmin.w, rMin);

    // arg = 1-|t-p| == (t ? p : 1-p) exactly; pred in (1e-6, 1-1e-6) => arg>0.
    float s;
    s  = fmaf(2.0f, b0, 1.0f) * __log2f(1.0f - fabsf(t.x - p.x));
    s += fmaf(2.0f, b1, 1.0f) * __log2f(1.0f - fabsf(t.y - p.y));
    s += fmaf(2.0f, b2, 1.0f) * __log2f(1.0f - fabsf(t.z - p.z));
    s += fmaf(2.0f, b3, 1.0f) * __log2f(1.0f - fabsf(t.w - p.w));
    return s;
}

__global__ __launch_bounds__(NTHR, 5)
void bab_fused(const float* __restrict__ pred, const float* __restrict__ target,
               float* __restrict__ out)
{
    const int tid  = threadIdx.x;
    const int lane = tid & 31;
    const int warp = tid >> 5;

    const int grp = blockIdx.x;
    const int img = grp / GRPS;
    const int y0  = (grp % GRPS) * RPB;

    const int x0 = warp * 128 + lane * 4;     // this thread's 4 columns

    // Merged halo: lane 0 tracks the LEFT halo column, lane 31 the RIGHT one.
    const int xH  = (lane == 0) ? (warp * 128 - 1) : (warp * 128 + 128);
    const bool doH = ((lane == 0) && (xH >= 0)) || ((lane == 31) && (xH < Wd));
    const float eMaxId = NEG_BIG, eMinId = POS_BIG;   // border identities

    const float* __restrict__ tb = target + (size_t)img * Hd * Wd;
    const float* __restrict__ pb = pred   + (size_t)img * Hd * Wd;

    // Rolling register window of target rows: prev (y-1), cur (y).
    // Border rows via index clamp (clamped row == pooling identity).
    const int ypInit = (y0 > 0) ? (y0 - 1) : 0;
    float4 cur  = *(const float4*)(tb + (size_t)y0 * Wd + x0);
    float4 prev = *(const float4*)(tb + (size_t)ypInit * Wd + x0);

    float curH = 0.f, prevH = 0.f;
    if (doH) { curH  = tb[(size_t)y0 * Wd + xH];
               prevH = tb[(size_t)ypInit * Wd + xH]; }

    float acc = 0.0f;

    // Two rows per iteration; pairwise-shared vertical extremes.
    #pragma unroll 2
    for (int r = 0; r < RPB; r += 2) {
        const int y   = y0 + r;
        const int yn1 = y + 1;                             // always < Hd in-block
        const int yn2 = (y + 2 < Hd) ? (y + 2) : (Hd - 1); // clamp -> identity

        // All loads up front (affine, unconditional for the float4s).
        const float4 nextA = *(const float4*)(tb + (size_t)yn1 * Wd + x0);
        const float4 nextB = *(const float4*)(tb + (size_t)yn2 * Wd + x0);
        const float4 pA    = *(const float4*)(pb + (size_t)y   * Wd + x0);
        const float4 pB    = *(const float4*)(pb + (size_t)yn1 * Wd + x0);
        const float nextAH = doH ? tb[(size_t)yn1 * Wd + xH] : 0.f;
        const float nextBH = doH ? tb[(size_t)yn2 * Wd + xH] : 0.f;

        // Shared pair extremes of (cur, nextA).
        float4 pmx, pmn;
        pmx.x = fmaxf(cur.x, nextA.x); pmn.x = fminf(cur.x, nextA.x);
        pmx.y = fmaxf(cur.y, nextA.y); pmn.y = fminf(cur.y, nextA.y);
        pmx.z = fmaxf(cur.z, nextA.z); pmn.z = fminf(cur.z, nextA.z);
        pmx.w = fmaxf(cur.w, nextA.w); pmn.w = fminf(cur.w, nextA.w);

        // Row A vertical extremes: (prev, cur, nextA) = op(prev, pair).
        float4 vmaxA, vminA, vmaxB, vminB;
        vmaxA.x = fmaxf(prev.x, pmx.x); vminA.x = fminf(prev.x, pmn.x);
        vmaxA.y = fmaxf(prev.y, pmx.y); vminA.y = fminf(prev.y, pmn.y);
        vmaxA.z = fmaxf(prev.z, pmx.z); vminA.z = fminf(prev.z, pmn.z);
        vmaxA.w = fmaxf(prev.w, pmx.w); vminA.w = fminf(prev.w, pmn.w);
        // Row B vertical extremes: (cur, nextA, nextB) = op(pair, nextB).
        vmaxB.x = fmaxf(nextB.x, pmx.x); vminB.x = fminf(nextB.x, pmn.x);
        vmaxB.y = fmaxf(nextB.y, pmx.y); vminB.y = fminf(nextB.y, pmn.y);
        vmaxB.z = fmaxf(nextB.z, pmx.z); vminB.z = fminf(nextB.z, pmn.z);
        vmaxB.w = fmaxf(nextB.w, pmx.w); vminB.w = fminf(nextB.w, pmn.w);

        // Halo-column vertical extremes for this lane's halo column.
        const float eMaxA = doH ? max3(prevH, curH, nextAH) : eMaxId;
        const float eMinA = doH ? min3(prevH, curH, nextAH) : eMinId;
        const float eMaxB = doH ? max3(curH, nextAH, nextBH) : eMaxId;
        const float eMinB = doH ? min3(curH, nextAH, nextBH) : eMinId;

        acc += row_loss(vmaxA, vminA, cur,   pA, eMaxA, eMinA, lane);
        acc += row_loss(vmaxB, vminB, nextA, pB, eMaxB, eMinB, lane);

        prev  = nextA;  cur  = nextB;
        prevH = nextAH; curH = nextBH;
    }

    acc *= NLN2;   // one scale: sum of w*log2(arg) -> sum of w*(-ln(arg))

    // ---- Block reduction: warp shuffle, then cross-warp via shared. ----
    #pragma unroll
    for (int off = 16; off > 0; off >>= 1)
        acc += __shfl_down_sync(FULLM, acc, off);

    __shared__ float swarp[NTHR / 32];
    if (lane == 0) swarp[warp] = acc;
    __syncthreads();
    if (tid == 0) {
        float v = 0.0f;
        #pragma unroll
        for (int i = 0; i < NTHR / 32; ++i) v += swarp[i];
        g_partials[blockIdx.x] = v;
    }

    // ---- Last-block fused finalize (deterministic order). ----
    __shared__ bool s_last;
    __threadfence();
    if (tid == 0) {
        unsigned int old = atomicAdd(&g_ticket, 1u);
        s_last = (old == NBLK - 1);
    }
    __syncthreads();

    if (s_last) {
        __shared__ double sd[NTHR];
        double s = 0.0;
        for (int i = tid; i < NBLK; i += NTHR)   // fixed order per thread
            s += (double)g_partials[i];
        sd[tid] = s;
        __syncthreads();
        #pragma unroll
        for (int stride = NTHR / 2; stride > 0; stride >>= 1) {
            if (tid < stride) sd[tid] += sd[tid + stride];
            __syncthreads();
        }
        if (tid == 0) {
            out[0] = (float)(sd[0] / (double)((size_t)Bd * Hd * Wd));
            g_ticket = 0;                        // reset for next launch/replay
        }
    }
}

extern "C" void kernel_launch(void* const* d_in, const int* in_sizes, int n_in,
                              void* d_out, int out_size)
{
    (void)in_sizes; (void)n_in; (void)out_size;
    const float* pred   = (const float*)d_in[0];
    const float* target = (const float*)d_in[1];
    float* out = (float*)d_out;

    bab_fused<<<NBLK, NTHR>>>(pred, target, out);
}